// round 15
// baseline (speedup 1.0000x reference)
#include <cuda_runtime.h>
#include <cuda_bf16.h>
#include <cstdint>

#define FM        64
#define MAXV      100000
#define MAXC      50000
#define MAXNNZ    2000000
#define OUTB      16

typedef unsigned long long u64;
typedef unsigned int u32;

// ===================== scratch globals ======================================
__device__ float g_vars[MAXV * FM];
__device__ float g_cons[MAXC * FM];
__device__ float g_v2c [MAXC * FM];
__device__ float g_c2v [MAXV * FM];

__device__ int   g_cntC[MAXC];
__device__ int   g_cntV[MAXV];
__device__ int   g_offC[MAXC + 1];
__device__ int   g_offV[MAXV + 1];
__device__ int   g_curC[MAXC];
__device__ int   g_curV[MAXV];

__device__ int   g_scanDone;
__device__ int   g_zeroDone = 0;

// packed edge entries: low 32 = feature-row offset (index*FM), high 32 = |val| bits
__device__ __align__(16) u64 g_cscE[MAXNNZ];
__device__ __align__(16) u64 g_csrE[MAXNNZ];

// packed per-lane weight fragments (uint4 = {b0_hi, b1_hi, b0_lo, b1_lo})
__device__ u32 g_w1p_cu[16384];
__device__ u32 g_w2p_cu[8192];
__device__ u32 g_w1p_vu[16384];
__device__ u32 g_w2p_vu[8192];
__device__ u32 g_w1p_out[8192];
__device__ u32 g_w2p_out[2048];

// ===================== helpers ==============================================
__device__ __forceinline__ void bfsplit2(float f0, float f1, u32& hi, u32& lo) {
    __nv_bfloat162 h, l;
    h.x = __float2bfloat16(f0);
    h.y = __float2bfloat16(f1);
    l.x = __float2bfloat16(f0 - __bfloat162float(h.x));
    l.y = __float2bfloat16(f1 - __bfloat162float(h.y));
    hi = *(u32*)&h;
    lo = *(u32*)&l;
}

__device__ __forceinline__ void mma_bf16(float* d, u32 a0, u32 a1, u32 a2, u32 a3,
                                         u32 b0, u32 b1) {
    asm volatile(
        "mma.sync.aligned.m16n8k16.row.col.f32.bf16.bf16.f32 "
        "{%0,%1,%2,%3}, {%4,%5,%6,%7}, {%8,%9}, {%0,%1,%2,%3};"
        : "+f"(d[0]), "+f"(d[1]), "+f"(d[2]), "+f"(d[3])
        : "r"(a0), "r"(a1), "r"(a2), "r"(a3), "r"(b0), "r"(b1));
}

// scalar layer-2 helper for the prep branch of the setup kernel
__device__ __forceinline__ void mlp_layer2_64(const float* sbuf,
                                              const float* __restrict__ W2,
                                              const float* __restrict__ b2,
                                              float* __restrict__ outp,
                                              int row0, int rows, int lane) {
    float2 acc[4];
#pragma unroll
    for (int r = 0; r < 4; r++) acc[r] = make_float2(0.f, 0.f);

    for (int k = 0; k < 128; k += 4) {
        float4 hv[4];
#pragma unroll
        for (int r = 0; r < 4; r++) hv[r] = *(const float4*)&sbuf[r * 128 + k];
#pragma unroll
        for (int kk = 0; kk < 4; kk++) {
            float2 w = *(const float2*)&W2[(k + kk) * 64 + 2 * lane];
#pragma unroll
            for (int r = 0; r < 4; r++) {
                float hk = ((const float*)&hv[r])[kk];
                acc[r].x += hk * w.x;
                acc[r].y += hk * w.y;
            }
        }
    }
    float2 bb = *(const float2*)&b2[2 * lane];
#pragma unroll
    for (int r = 0; r < 4; r++) {
        if (row0 + r < rows) {
            *(float2*)&outp[(size_t)(row0 + r) * 64 + 2 * lane] =
                make_float2(acc[r].x + bb.x, acc[r].y + bb.y);
        }
    }
}

// ===================== fused setup kernel (+ histogram via spin-flag) =======
// Block ranges:
//   [0, gZ)        zero counts  -> signal g_zeroDone
//   [gZ, +gI)      init vars
//   [+0, +128)     conv_w cu/vu
//   [+128, +160)   conv_w_out
//   [+160, +gP)    prepare_cond MLP
//   [+gP, +gH)     histogram (spins on g_zeroDone == gZ)
__global__ void __launch_bounds__(256) setup_kernel(
        int gZ, int gI, int gP, int gH, int C, int V, int nnz,
        const int* __restrict__ rowI, const int* __restrict__ colI,
        const float* __restrict__ cond,
        const float* __restrict__ pc_w1, const float* __restrict__ pc_b1,
        const float* __restrict__ pc_w2, const float* __restrict__ pc_b2,
        const float* __restrict__ cu_w1, const float* __restrict__ cu_w2,
        const float* __restrict__ vu_w1, const float* __restrict__ vu_w2,
        const float* __restrict__ o_w1,  const float* __restrict__ o_w2) {
    __shared__ float sbuf[8][512];
    int b   = blockIdx.x;
    int tid = threadIdx.x;

    if (b == 0 && tid == 0) g_scanDone = 0;

    if (b < gZ) {
        int i = b * 256 + tid;
        if (i < C) g_cntC[i] = 0;
        if (i < V) g_cntV[i] = 0;
        __threadfence();
        __syncthreads();
        if (tid == 0) atomicAdd(&g_zeroDone, 1);
        return;
    }
    b -= gZ;

    if (b < gI) {
        int i = b * 256 + tid;
        if (i < V * FM) g_vars[i] = 1.0f;
        return;
    }
    b -= gI;

    if (b < 128) {   // conv_w for cu (first 64 blocks) and vu (next 64)
        const float* W1 = (b < 64) ? cu_w1 : vu_w1;
        const float* W2 = (b < 64) ? cu_w2 : vu_w2;
        u32* w1p = (b < 64) ? g_w1p_cu : g_w1p_vu;
        u32* w2p = (b < 64) ? g_w2p_cu : g_w2p_vu;
        int idx = (b & 63) * 256 + tid;     // 0..16383
        {
            int pos  = idx & 3;
            int lane = (idx >> 2) & 31;
            int j    = (idx >> 7) & 15;
            int t    = idx >> 11;
            int k = t * 16 + 2 * (lane & 3) + ((pos & 1) ? 8 : 0);
            int n = j * 8 + (lane >> 2);
            float f0 = W1[k * 128 + n];
            float f1 = W1[(k + 1) * 128 + n];
            u32 hi, lo;
            bfsplit2(f0, f1, hi, lo);
            w1p[idx] = (pos >= 2) ? lo : hi;
        }
        if (idx < 8192) {
            int pos  = idx & 3;
            int lane = (idx >> 2) & 31;
            int j    = (idx >> 7) & 7;
            int t    = idx >> 10;
            int k = t * 16 + 2 * (lane & 3) + ((pos & 1) ? 8 : 0);
            int n = j * 8 + (lane >> 2);
            float f0 = W2[k * 64 + n];
            float f1 = W2[(k + 1) * 64 + n];
            u32 hi, lo;
            bfsplit2(f0, f1, hi, lo);
            w2p[idx] = (pos >= 2) ? lo : hi;
        }
        return;
    }
    b -= 128;

    if (b < 32) {    // conv_w_out
        int idx = b * 256 + tid;            // 0..8191
        {
            int pos  = idx & 3;
            int lane = (idx >> 2) & 31;
            int j    = (idx >> 7) & 15;
            int t    = idx >> 11;           // 0..3
            int k = t * 16 + 2 * (lane & 3) + ((pos & 1) ? 8 : 0);
            int n = j * 8 + (lane >> 2);
            float f0 = o_w1[k * 128 + n];
            float f1 = o_w1[(k + 1) * 128 + n];
            u32 hi, lo;
            bfsplit2(f0, f1, hi, lo);
            g_w1p_out[idx] = (pos >= 2) ? lo : hi;
        }
        if (idx < 2048) {
            int pos  = idx & 3;
            int lane = (idx >> 2) & 31;
            int j    = (idx >> 7) & 1;
            int t    = idx >> 8;            // 0..7
            int k = t * 16 + 2 * (lane & 3) + ((pos & 1) ? 8 : 0);
            int n = j * 8 + (lane >> 2);
            float f0 = o_w2[k * 16 + n];
            float f1 = o_w2[(k + 1) * 16 + n];
            u32 hi, lo;
            bfsplit2(f0, f1, hi, lo);
            g_w2p_out[idx] = (pos >= 2) ? lo : hi;
        }
        return;
    }
    b -= 32;

    if (b < gP) {    // prepare_cond: scalar -> 128(relu) -> 64 into g_cons
        int warp = tid >> 5;
        int lane = tid & 31;
        int row0 = (b * 8 + warp) * 4;
        if (row0 >= C) return;
        float* sbf = sbuf[warp];

        float4 w = *(const float4*)&pc_w1[4 * lane];
        float4 bb = *(const float4*)&pc_b1[4 * lane];
#pragma unroll
        for (int r = 0; r < 4; r++) {
            int row = min(row0 + r, C - 1);
            float c = cond[row];
            float4 h;
            h.x = fmaxf(c * w.x + bb.x, 0.f);
            h.y = fmaxf(c * w.y + bb.y, 0.f);
            h.z = fmaxf(c * w.z + bb.z, 0.f);
            h.w = fmaxf(c * w.w + bb.w, 0.f);
            *(float4*)&sbf[r * 128 + 4 * lane] = h;
        }
        __syncwarp();
        mlp_layer2_64(sbf, pc_w2, pc_b2, g_cons, row0, C, lane);
        return;
    }
    b -= gP;

    if (b < gH) {    // histogram: wait for zeroing, then count
        if (tid == 0) {
            while (atomicAdd(&g_zeroDone, 0) < gZ) __nanosleep(100);
        }
        __syncthreads();
        int base = b * 256 * 8 + tid;
#pragma unroll
        for (int j = 0; j < 8; j++) {
            int e = base + j * 256;
            if (e < nnz) {
                atomicAdd(&g_cntC[colI[e]], 1);
                atomicAdd(&g_cntV[rowI[e]], 1);
            }
        }
    }
}

// ===================== CSR/CSC build ========================================
// fill with inlined scan: blocks 0/1 scan C/V sides, publish via flag; all
// blocks then place edges (indices stored PRE-SCALED by FM).
__global__ void __launch_bounds__(256) fill_kernel(
        const int* __restrict__ row, const int* __restrict__ col,
        const float* __restrict__ av, int nnz, int nC, int nV) {
    __shared__ int part[256];
    int tid = threadIdx.x;

    if (blockIdx.x < 2) {
        const int* cnt; int* off; int* cur; int n;
        if (blockIdx.x == 0) { cnt = g_cntC; off = g_offC; cur = g_curC; n = nC; }
        else                 { cnt = g_cntV; off = g_offV; cur = g_curV; n = nV; }

        int chunk = (n + 255) / 256;
        int beg = tid * chunk;
        int end = min(n, beg + chunk);

        int s = 0;
        for (int i = beg; i < end; i++) s += cnt[i];
        part[tid] = s;
        __syncthreads();
        for (int d = 1; d < 256; d <<= 1) {
            int v = (tid >= d) ? part[tid - d] : 0;
            __syncthreads();
            part[tid] += v;
            __syncthreads();
        }
        int run = (tid == 0) ? 0 : part[tid - 1];
        for (int i = beg; i < end; i++) {
            off[i] = run; cur[i] = run;
            run += cnt[i];
        }
        if (tid == 255) off[n] = part[255];
        __syncthreads();
        if (tid == 0) {
            __threadfence();
            atomicAdd(&g_scanDone, 1);
        }
    }

    if (tid == 0) {
        while (atomicAdd(&g_scanDone, 0) < 2) __nanosleep(100);
    }
    __syncthreads();

    int base = blockIdx.x * blockDim.x * 4 + tid;
    int e[4], r[4], c[4];
    u32 vb[4];
    bool ok[4];
#pragma unroll
    for (int j = 0; j < 4; j++) {
        e[j] = base + j * blockDim.x;
        ok[j] = e[j] < nnz;
        if (ok[j]) {
            r[j] = row[e[j]];
            c[j] = col[e[j]];
            vb[j] = __float_as_uint(fabsf(av[e[j]]));
        }
    }
    int p[4], q[4];
#pragma unroll
    for (int j = 0; j < 4; j++) {
        if (ok[j]) {
            p[j] = atomicAdd(&g_curC[c[j]], 1);
            q[j] = atomicAdd(&g_curV[r[j]], 1);
        }
    }
#pragma unroll
    for (int j = 0; j < 4; j++) {
        if (ok[j]) {
            g_cscE[p[j]] = ((u64)vb[j] << 32) | (u32)(r[j] * FM);
            g_csrE[q[j]] = ((u64)vb[j] << 32) | (u32)(c[j] * FM);
        }
    }
}

// ===================== segment gather-reduce (warp per segment) ============
// Edge low-32 is pre-scaled (index*FM). Edges loaded 2-at-a-time via LDG.128
// (arrays are 16B-aligned; odd segment starts peeled).
__global__ void seg_gather_kernel(const int* __restrict__ offs,
                                  const u64* __restrict__ edges,
                                  const float* __restrict__ srcF,
                                  float* __restrict__ dstF, int nseg) {
    int warp = threadIdx.x >> 5;
    int lane = threadIdx.x & 31;
    int seg  = blockIdx.x * (blockDim.x >> 5) + warp;
    if (seg >= nseg) return;

    const float* src2 = srcF + 2 * lane;

    int s = offs[seg], e = offs[seg + 1];
    float ax = 0.f, ay = 0.f;
    int p = s;

    if (p < e && (p & 1)) {
        u64 e0 = __ldg(&edges[p]);
        float2 f0 = *(const float2*)&src2[(u32)e0];
        float v0 = __uint_as_float((u32)(e0 >> 32));
        ax += v0 * f0.x; ay += v0 * f0.y;
        p++;
    }
    for (; p + 4 <= e; p += 4) {
        uint4 a = __ldg((const uint4*)&edges[p]);
        uint4 b = __ldg((const uint4*)&edges[p + 2]);
        float2 f0 = *(const float2*)&src2[a.x];
        float2 f1 = *(const float2*)&src2[a.z];
        float2 f2 = *(const float2*)&src2[b.x];
        float2 f3 = *(const float2*)&src2[b.z];
        float v0 = __uint_as_float(a.y);
        float v1 = __uint_as_float(a.w);
        float v2 = __uint_as_float(b.y);
        float v3 = __uint_as_float(b.w);
        ax += v0 * f0.x; ay += v0 * f0.y;
        ax += v1 * f1.x; ay += v1 * f1.y;
        ax += v2 * f2.x; ay += v2 * f2.y;
        ax += v3 * f3.x; ay += v3 * f3.y;
    }
    for (; p < e; p++) {
        u64 e0 = __ldg(&edges[p]);
        float2 f0 = *(const float2*)&src2[(u32)e0];
        float v0 = __uint_as_float((u32)(e0 >> 32));
        ax += v0 * f0.x; ay += v0 * f0.y;
    }
    *(float2*)&dstF[(size_t)seg * FM + 2 * lane] = make_float2(ax, ay);
}

// ===================== MMA MLP: concat(inA,inB)->128(relu)->64 ==============
__global__ void __launch_bounds__(256) mlp_mma_kernel(
        const float* __restrict__ inA, const float* __restrict__ inB,
        float* __restrict__ outp,
        const uint4* __restrict__ w1p, const float* __restrict__ b1,
        const uint4* __restrict__ w2p, const float* __restrict__ b2,
        int rows) {
    int tid = threadIdx.x;
    int wid = tid >> 5;
    int lane = tid & 31;
    int m = lane & 3;
    int g = lane >> 2;

    int rbase = blockIdx.x * 128 + wid * 16;
    if (rbase >= rows) return;
    int r0 = rbase + g, r1 = rbase + g + 8;
    int rr0 = min(r0, rows - 1), rr1 = min(r1, rows - 1);

    float d1[16][4];
#pragma unroll
    for (int j = 0; j < 16; j++)
#pragma unroll
        for (int q = 0; q < 4; q++) d1[j][q] = 0.f;

#pragma unroll
    for (int t = 0; t < 8; t++) {
        const float* src = (t < 4) ? inA : inB;
        int kc = (t & 3) * 16 + 2 * m;
        float2 x0 = *(const float2*)&src[(size_t)rr0 * 64 + kc];
        float2 x1 = *(const float2*)&src[(size_t)rr1 * 64 + kc];
        float2 x2 = *(const float2*)&src[(size_t)rr0 * 64 + kc + 8];
        float2 x3 = *(const float2*)&src[(size_t)rr1 * 64 + kc + 8];
        u32 ah0, al0, ah1, al1, ah2, al2, ah3, al3;
        bfsplit2(x0.x, x0.y, ah0, al0);
        bfsplit2(x1.x, x1.y, ah1, al1);
        bfsplit2(x2.x, x2.y, ah2, al2);
        bfsplit2(x3.x, x3.y, ah3, al3);

        const uint4* wp = w1p + (size_t)(t * 16) * 32 + lane;
#pragma unroll
        for (int j = 0; j < 16; j++) {
            uint4 w = __ldg(&wp[j * 32]);
            mma_bf16(d1[j], ah0, ah1, ah2, ah3, w.x, w.y);
            mma_bf16(d1[j], ah0, ah1, ah2, ah3, w.z, w.w);
            mma_bf16(d1[j], al0, al1, al2, al3, w.x, w.y);
        }
    }

    float d2[8][4];
#pragma unroll
    for (int j = 0; j < 8; j++)
#pragma unroll
        for (int q = 0; q < 4; q++) d2[j][q] = 0.f;

#pragma unroll
    for (int t = 0; t < 8; t++) {
        float2 ba = *(const float2*)&b1[16 * t + 2 * m];
        float2 bb = *(const float2*)&b1[16 * t + 8 + 2 * m];
        float f0 = fmaxf(d1[2 * t][0] + ba.x, 0.f);
        float f1 = fmaxf(d1[2 * t][1] + ba.y, 0.f);
        float f2 = fmaxf(d1[2 * t][2] + ba.x, 0.f);
        float f3 = fmaxf(d1[2 * t][3] + ba.y, 0.f);
        float f4 = fmaxf(d1[2 * t + 1][0] + bb.x, 0.f);
        float f5 = fmaxf(d1[2 * t + 1][1] + bb.y, 0.f);
        float f6 = fmaxf(d1[2 * t + 1][2] + bb.x, 0.f);
        float f7 = fmaxf(d1[2 * t + 1][3] + bb.y, 0.f);
        u32 ah0, al0, ah1, al1, ah2, al2, ah3, al3;
        bfsplit2(f0, f1, ah0, al0);
        bfsplit2(f2, f3, ah1, al1);
        bfsplit2(f4, f5, ah2, al2);
        bfsplit2(f6, f7, ah3, al3);

        const uint4* wp = w2p + (size_t)(t * 8) * 32 + lane;
#pragma unroll
        for (int j = 0; j < 8; j++) {
            uint4 w = __ldg(&wp[j * 32]);
            mma_bf16(d2[j], ah0, ah1, ah2, ah3, w.x, w.y);
            mma_bf16(d2[j], ah0, ah1, ah2, ah3, w.z, w.w);
            mma_bf16(d2[j], al0, al1, al2, al3, w.x, w.y);
        }
    }

#pragma unroll
    for (int j = 0; j < 8; j++) {
        float2 b = *(const float2*)&b2[8 * j + 2 * m];
        if (r0 < rows) {
            *(float2*)&outp[(size_t)r0 * 64 + 8 * j + 2 * m] =
                make_float2(d2[j][0] + b.x, d2[j][1] + b.y);
        }
        if (r1 < rows) {
            *(float2*)&outp[(size_t)r1 * 64 + 8 * j + 2 * m] =
                make_float2(d2[j][2] + b.x, d2[j][3] + b.y);
        }
    }
}

// ===================== MMA output MLP: vars[64]->128(relu)->16 + sigmoid ====
__global__ void __launch_bounds__(256) out_mma_kernel(
        const uint4* __restrict__ w1p, const float* __restrict__ b1,
        const uint4* __restrict__ w2p, const float* __restrict__ b2,
        float* __restrict__ outp, int rows) {
    int tid = threadIdx.x;
    int wid = tid >> 5;
    int lane = tid & 31;
    int m = lane & 3;
    int g = lane >> 2;

    if (blockIdx.x == 0 && tid == 0) g_zeroDone = 0;   // reset for next replay

    int rbase = blockIdx.x * 128 + wid * 16;
    if (rbase >= rows) return;
    int r0 = rbase + g, r1 = rbase + g + 8;
    int rr0 = min(r0, rows - 1), rr1 = min(r1, rows - 1);

    float d1[16][4];
#pragma unroll
    for (int j = 0; j < 16; j++)
#pragma unroll
        for (int q = 0; q < 4; q++) d1[j][q] = 0.f;

#pragma unroll
    for (int t = 0; t < 4; t++) {
        int kc = t * 16 + 2 * m;
        float2 x0 = *(const float2*)&g_vars[(size_t)rr0 * 64 + kc];
        float2 x1 = *(const float2*)&g_vars[(size_t)rr1 * 64 + kc];
        float2 x2 = *(const float2*)&g_vars[(size_t)rr0 * 64 + kc + 8];
        float2 x3 = *(const float2*)&g_vars[(size_t)rr1 * 64 + kc + 8];
        u32 ah0, al0, ah1, al1, ah2, al2, ah3, al3;
        bfsplit2(x0.x, x0.y, ah0, al0);
        bfsplit2(x1.x, x1.y, ah1, al1);
        bfsplit2(x2.x, x2.y, ah2, al2);
        bfsplit2(x3.x, x3.y, ah3, al3);

        const uint4* wp = w1p + (size_t)(t * 16) * 32 + lane;
#pragma unroll
        for (int j = 0; j < 16; j++) {
            uint4 w = __ldg(&wp[j * 32]);
            mma_bf16(d1[j], ah0, ah1, ah2, ah3, w.x, w.y);
            mma_bf16(d1[j], ah0, ah1, ah2, ah3, w.z, w.w);
            mma_bf16(d1[j], al0, al1, al2, al3, w.x, w.y);
        }
    }

    float d2[2][4];
#pragma unroll
    for (int j = 0; j < 2; j++)
#pragma unroll
        for (int q = 0; q < 4; q++) d2[j][q] = 0.f;

#pragma unroll
    for (int t = 0; t < 8; t++) {
        float2 ba = *(const float2*)&b1[16 * t + 2 * m];
        float2 bb = *(const float2*)&b1[16 * t + 8 + 2 * m];
        float f0 = fmaxf(d1[2 * t][0] + ba.x, 0.f);
        float f1 = fmaxf(d1[2 * t][1] + ba.y, 0.f);
        float f2 = fmaxf(d1[2 * t][2] + ba.x, 0.f);
        float f3 = fmaxf(d1[2 * t][3] + ba.y, 0.f);
        float f4 = fmaxf(d1[2 * t + 1][0] + bb.x, 0.f);
        float f5 = fmaxf(d1[2 * t + 1][1] + bb.y, 0.f);
        float f6 = fmaxf(d1[2 * t + 1][2] + bb.x, 0.f);
        float f7 = fmaxf(d1[2 * t + 1][3] + bb.y, 0.f);
        u32 ah0, al0, ah1, al1, ah2, al2, ah3, al3;
        bfsplit2(f0, f1, ah0, al0);
        bfsplit2(f2, f3, ah1, al1);
        bfsplit2(f4, f5, ah2, al2);
        bfsplit2(f6, f7, ah3, al3);

        const uint4* wp = w2p + (size_t)(t * 2) * 32 + lane;
#pragma unroll
        for (int j = 0; j < 2; j++) {
            uint4 w = __ldg(&wp[j * 32]);
            mma_bf16(d2[j], ah0, ah1, ah2, ah3, w.x, w.y);
            mma_bf16(d2[j], ah0, ah1, ah2, ah3, w.z, w.w);
            mma_bf16(d2[j], al0, al1, al2, al3, w.x, w.y);
        }
    }

#pragma unroll
    for (int j = 0; j < 2; j++) {
        float2 b = *(const float2*)&b2[8 * j + 2 * m];
        if (r0 < rows) {
            float z0 = d2[j][0] + b.x;
            float z1 = d2[j][1] + b.y;
            *(float2*)&outp[(size_t)r0 * OUTB + 8 * j + 2 * m] =
                make_float2(1.f / (1.f + __expf(-z0)), 1.f / (1.f + __expf(-z1)));
        }
        if (r1 < rows) {
            float z2 = d2[j][2] + b.x;
            float z3 = d2[j][3] + b.y;
            *(float2*)&outp[(size_t)r1 * OUTB + 8 * j + 2 * m] =
                make_float2(1.f / (1.f + __expf(-z2)), 1.f / (1.f + __expf(-z3)));
        }
    }
}

// ===================== launch ===============================================
extern "C" void kernel_launch(void* const* d_in, const int* in_sizes, int n_in,
                              void* d_out, int out_size) {
    const int*   row  = (const int*)  d_in[0];
    const int*   col  = (const int*)  d_in[1];
    const float* adj  = (const float*)d_in[2];
    const float* cond = (const float*)d_in[3];

    int nnz = in_sizes[0];
    int C   = in_sizes[3];
    int V   = out_size / OUTB;
    if (nnz > MAXNNZ) nnz = MAXNNZ;
    if (C > MAXC) C = MAXC;
    if (V > MAXV) V = MAXV;

    int w = 4;
    if (n_in >= 22 && in_sizes[4] == 1 && in_sizes[5] == 1) w = 6;
    const float* pc_w1 = (const float*)d_in[w + 0];
    const float* pc_b1 = (const float*)d_in[w + 1];
    const float* pc_w2 = (const float*)d_in[w + 2];
    const float* pc_b2 = (const float*)d_in[w + 3];
    const float* cu_w1 = (const float*)d_in[w + 4];
    const float* cu_b1 = (const float*)d_in[w + 5];
    const float* cu_w2 = (const float*)d_in[w + 6];
    const float* cu_b2 = (const float*)d_in[w + 7];
    const float* vu_w1 = (const float*)d_in[w + 8];
    const float* vu_b1 = (const float*)d_in[w + 9];
    const float* vu_w2 = (const float*)d_in[w + 10];
    const float* vu_b2 = (const float*)d_in[w + 11];
    const float* o_w1  = (const float*)d_in[w + 12];
    const float* o_b1  = (const float*)d_in[w + 13];
    const float* o_w2  = (const float*)d_in[w + 14];
    const float* o_b2  = (const float*)d_in[w + 15];

    float *p_vars, *p_cons, *p_v2c, *p_c2v;
    int   *p_offC, *p_offV;
    u64   *p_cscE, *p_csrE;
    u32   *p_w1cu, *p_w2cu, *p_w1vu, *p_w2vu, *p_w1o, *p_w2o;
    cudaGetSymbolAddress((void**)&p_vars,  g_vars);
    cudaGetSymbolAddress((void**)&p_cons,  g_cons);
    cudaGetSymbolAddress((void**)&p_v2c,   g_v2c);
    cudaGetSymbolAddress((void**)&p_c2v,   g_c2v);
    cudaGetSymbolAddress((void**)&p_offC,  g_offC);
    cudaGetSymbolAddress((void**)&p_offV,  g_offV);
    cudaGetSymbolAddress((void**)&p_cscE,  g_cscE);
    cudaGetSymbolAddress((void**)&p_csrE,  g_csrE);
    cudaGetSymbolAddress((void**)&p_w1cu,  g_w1p_cu);
    cudaGetSymbolAddress((void**)&p_w2cu,  g_w2p_cu);
    cudaGetSymbolAddress((void**)&p_w1vu,  g_w1p_vu);
    cudaGetSymbolAddress((void**)&p_w2vu,  g_w2p_vu);
    cudaGetSymbolAddress((void**)&p_w1o,   g_w1p_out);
    cudaGetSymbolAddress((void**)&p_w2o,   g_w2p_out);

    int maxCV = (C > V) ? C : V;
    int gZ = (maxCV + 255) / 256;
    int gI = (V * FM + 255) / 256;
    int gP = (C + 31) / 32;
    int gH = (nnz + 2047) / 2048;
    int gridSetup = gZ + gI + 128 + 32 + gP + gH;

    setup_kernel<<<gridSetup, 256>>>(gZ, gI, gP, gH, C, V, nnz, row, col, cond,
                                     pc_w1, pc_b1, pc_w2, pc_b2,
                                     cu_w1, cu_w2, vu_w1, vu_w2, o_w1, o_w2);
    fill_kernel<<<(nnz + 1023) / 1024, 256>>>(row, col, adj, nnz, C, V);

    int gC = (C + 127) / 128;
    int gV = (V + 127) / 128;
    for (int it = 0; it < 3; it++) {
        seg_gather_kernel<<<(C + 7) / 8, 256>>>(p_offC, p_cscE, p_vars, p_v2c, C);
        mlp_mma_kernel<<<gC, 256>>>(p_cons, p_v2c, p_cons,
                                    (const uint4*)p_w1cu, cu_b1, (const uint4*)p_w2cu, cu_b2, C);
        seg_gather_kernel<<<(V + 7) / 8, 256>>>(p_offV, p_csrE, p_cons, p_c2v, V);
        mlp_mma_kernel<<<gV, 256>>>(p_vars, p_c2v, p_vars,
                                    (const uint4*)p_w1vu, vu_b1, (const uint4*)p_w2vu, vu_b2, V);
    }

    out_mma_kernel<<<(V + 127) / 128, 256>>>((const uint4*)p_w1o, o_b1,
                                             (const uint4*)p_w2o, o_b2,
                                             (float*)d_out, V);
}

// round 16
// speedup vs baseline: 1.0587x; 1.0587x over previous
#include <cuda_runtime.h>
#include <cuda_bf16.h>
#include <cstdint>

#define FM        64
#define MAXV      100000
#define MAXC      50000
#define MAXNNZ    2000000
#define OUTB      16

typedef unsigned long long u64;
typedef unsigned int u32;

// ===================== scratch globals ======================================
__device__ float g_vars[MAXV * FM];
__device__ float g_cons[MAXC * FM];
__device__ float g_v2c [MAXC * FM];
__device__ float g_c2v [MAXV * FM];

__device__ int   g_cntC[MAXC];
__device__ int   g_cntV[MAXV];
__device__ int   g_offC[MAXC + 1];
__device__ int   g_offV[MAXV + 1];
__device__ int   g_curC[MAXC];
__device__ int   g_curV[MAXV];

__device__ int   g_scanDone;

// packed edge entries: low 32 = feature-row offset (index*FM), high 32 = |val| bits
__device__ u64   g_cscE[MAXNNZ];
__device__ u64   g_csrE[MAXNNZ];

// packed per-lane weight fragments (uint4 = {b0_hi, b1_hi, b0_lo, b1_lo})
__device__ u32 g_w1p_cu[16384];
__device__ u32 g_w2p_cu[8192];
__device__ u32 g_w1p_vu[16384];
__device__ u32 g_w2p_vu[8192];
__device__ u32 g_w1p_out[8192];
__device__ u32 g_w2p_out[2048];

// ===================== helpers ==============================================
__device__ __forceinline__ void bfsplit2(float f0, float f1, u32& hi, u32& lo) {
    __nv_bfloat162 h, l;
    h.x = __float2bfloat16(f0);
    h.y = __float2bfloat16(f1);
    l.x = __float2bfloat16(f0 - __bfloat162float(h.x));
    l.y = __float2bfloat16(f1 - __bfloat162float(h.y));
    hi = *(u32*)&h;
    lo = *(u32*)&l;
}

__device__ __forceinline__ void mma_bf16(float* d, u32 a0, u32 a1, u32 a2, u32 a3,
                                         u32 b0, u32 b1) {
    asm volatile(
        "mma.sync.aligned.m16n8k16.row.col.f32.bf16.bf16.f32 "
        "{%0,%1,%2,%3}, {%4,%5,%6,%7}, {%8,%9}, {%0,%1,%2,%3};"
        : "+f"(d[0]), "+f"(d[1]), "+f"(d[2]), "+f"(d[3])
        : "r"(a0), "r"(a1), "r"(a2), "r"(a3), "r"(b0), "r"(b1));
}

// scalar layer-2 helper for the prep branch of the setup kernel
__device__ __forceinline__ void mlp_layer2_64(const float* sbuf,
                                              const float* __restrict__ W2,
                                              const float* __restrict__ b2,
                                              float* __restrict__ outp,
                                              int row0, int rows, int lane) {
    float2 acc[4];
#pragma unroll
    for (int r = 0; r < 4; r++) acc[r] = make_float2(0.f, 0.f);

    for (int k = 0; k < 128; k += 4) {
        float4 hv[4];
#pragma unroll
        for (int r = 0; r < 4; r++) hv[r] = *(const float4*)&sbuf[r * 128 + k];
#pragma unroll
        for (int kk = 0; kk < 4; kk++) {
            float2 w = *(const float2*)&W2[(k + kk) * 64 + 2 * lane];
#pragma unroll
            for (int r = 0; r < 4; r++) {
                float hk = ((const float*)&hv[r])[kk];
                acc[r].x += hk * w.x;
                acc[r].y += hk * w.y;
            }
        }
    }
    float2 bb = *(const float2*)&b2[2 * lane];
#pragma unroll
    for (int r = 0; r < 4; r++) {
        if (row0 + r < rows) {
            *(float2*)&outp[(size_t)(row0 + r) * 64 + 2 * lane] =
                make_float2(acc[r].x + bb.x, acc[r].y + bb.y);
        }
    }
}

// ===================== fused setup kernel ====================================
__global__ void __launch_bounds__(256) setup_kernel(
        int gZ, int gI, int gP, int C, int V,
        const float* __restrict__ cond,
        const float* __restrict__ pc_w1, const float* __restrict__ pc_b1,
        const float* __restrict__ pc_w2, const float* __restrict__ pc_b2,
        const float* __restrict__ cu_w1, const float* __restrict__ cu_w2,
        const float* __restrict__ vu_w1, const float* __restrict__ vu_w2,
        const float* __restrict__ o_w1,  const float* __restrict__ o_w2) {
    __shared__ float sbuf[8][512];
    int b   = blockIdx.x;
    int tid = threadIdx.x;

    if (b == 0 && tid == 0) g_scanDone = 0;

    if (b < gZ) {
        int i = b * 256 + tid;
        if (i < C) g_cntC[i] = 0;
        if (i < V) g_cntV[i] = 0;
        return;
    }
    b -= gZ;

    if (b < gI) {
        int i = b * 256 + tid;
        if (i < V * FM) g_vars[i] = 1.0f;
        return;
    }
    b -= gI;

    if (b < 128) {   // conv_w for cu (first 64 blocks) and vu (next 64)
        const float* W1 = (b < 64) ? cu_w1 : vu_w1;
        const float* W2 = (b < 64) ? cu_w2 : vu_w2;
        u32* w1p = (b < 64) ? g_w1p_cu : g_w1p_vu;
        u32* w2p = (b < 64) ? g_w2p_cu : g_w2p_vu;
        int idx = (b & 63) * 256 + tid;     // 0..16383
        {
            int pos  = idx & 3;
            int lane = (idx >> 2) & 31;
            int j    = (idx >> 7) & 15;
            int t    = idx >> 11;
            int k = t * 16 + 2 * (lane & 3) + ((pos & 1) ? 8 : 0);
            int n = j * 8 + (lane >> 2);
            float f0 = W1[k * 128 + n];
            float f1 = W1[(k + 1) * 128 + n];
            u32 hi, lo;
            bfsplit2(f0, f1, hi, lo);
            w1p[idx] = (pos >= 2) ? lo : hi;
        }
        if (idx < 8192) {
            int pos  = idx & 3;
            int lane = (idx >> 2) & 31;
            int j    = (idx >> 7) & 7;
            int t    = idx >> 10;
            int k = t * 16 + 2 * (lane & 3) + ((pos & 1) ? 8 : 0);
            int n = j * 8 + (lane >> 2);
            float f0 = W2[k * 64 + n];
            float f1 = W2[(k + 1) * 64 + n];
            u32 hi, lo;
            bfsplit2(f0, f1, hi, lo);
            w2p[idx] = (pos >= 2) ? lo : hi;
        }
        return;
    }
    b -= 128;

    if (b < 32) {    // conv_w_out
        int idx = b * 256 + tid;            // 0..8191
        {
            int pos  = idx & 3;
            int lane = (idx >> 2) & 31;
            int j    = (idx >> 7) & 15;
            int t    = idx >> 11;           // 0..3
            int k = t * 16 + 2 * (lane & 3) + ((pos & 1) ? 8 : 0);
            int n = j * 8 + (lane >> 2);
            float f0 = o_w1[k * 128 + n];
            float f1 = o_w1[(k + 1) * 128 + n];
            u32 hi, lo;
            bfsplit2(f0, f1, hi, lo);
            g_w1p_out[idx] = (pos >= 2) ? lo : hi;
        }
        if (idx < 2048) {
            int pos  = idx & 3;
            int lane = (idx >> 2) & 31;
            int j    = (idx >> 7) & 1;
            int t    = idx >> 8;            // 0..7
            int k = t * 16 + 2 * (lane & 3) + ((pos & 1) ? 8 : 0);
            int n = j * 8 + (lane >> 2);
            float f0 = o_w2[k * 16 + n];
            float f1 = o_w2[(k + 1) * 16 + n];
            u32 hi, lo;
            bfsplit2(f0, f1, hi, lo);
            g_w2p_out[idx] = (pos >= 2) ? lo : hi;
        }
        return;
    }
    b -= 32;

    if (b < gP) {    // prepare_cond: scalar -> 128(relu) -> 64 into g_cons
        int warp = tid >> 5;
        int lane = tid & 31;
        int row0 = (b * 8 + warp) * 4;
        if (row0 >= C) return;
        float* sbf = sbuf[warp];

        float4 w = *(const float4*)&pc_w1[4 * lane];
        float4 bb = *(const float4*)&pc_b1[4 * lane];
#pragma unroll
        for (int r = 0; r < 4; r++) {
            int row = min(row0 + r, C - 1);
            float c = cond[row];
            float4 h;
            h.x = fmaxf(c * w.x + bb.x, 0.f);
            h.y = fmaxf(c * w.y + bb.y, 0.f);
            h.z = fmaxf(c * w.z + bb.z, 0.f);
            h.w = fmaxf(c * w.w + bb.w, 0.f);
            *(float4*)&sbf[r * 128 + 4 * lane] = h;
        }
        __syncwarp();
        mlp_layer2_64(sbf, pc_w2, pc_b2, g_cons, row0, C, lane);
    }
}

// ===================== CSR/CSC build ========================================
__global__ void hist_kernel(const int* __restrict__ row, const int* __restrict__ col, int nnz) {
    int base = blockIdx.x * blockDim.x * 8 + threadIdx.x;
#pragma unroll
    for (int j = 0; j < 8; j++) {
        int e = base + j * blockDim.x;
        if (e < nnz) {
            atomicAdd(&g_cntC[col[e]], 1);
            atomicAdd(&g_cntV[row[e]], 1);
        }
    }
}

// fill with inlined scan: blocks 0/1 scan C/V sides, publish via flag; all
// blocks then place edges (indices stored PRE-SCALED by FM).
__global__ void __launch_bounds__(256) fill_kernel(
        const int* __restrict__ row, const int* __restrict__ col,
        const float* __restrict__ av, int nnz, int nC, int nV) {
    __shared__ int part[256];
    int tid = threadIdx.x;

    if (blockIdx.x < 2) {
        const int* cnt; int* off; int* cur; int n;
        if (blockIdx.x == 0) { cnt = g_cntC; off = g_offC; cur = g_curC; n = nC; }
        else                 { cnt = g_cntV; off = g_offV; cur = g_curV; n = nV; }

        int chunk = (n + 255) / 256;
        int beg = tid * chunk;
        int end = min(n, beg + chunk);

        int s = 0;
        for (int i = beg; i < end; i++) s += cnt[i];
        part[tid] = s;
        __syncthreads();
        for (int d = 1; d < 256; d <<= 1) {
            int v = (tid >= d) ? part[tid - d] : 0;
            __syncthreads();
            part[tid] += v;
            __syncthreads();
        }
        int run = (tid == 0) ? 0 : part[tid - 1];
        for (int i = beg; i < end; i++) {
            off[i] = run; cur[i] = run;
            run += cnt[i];
        }
        if (tid == 255) off[n] = part[255];
        __syncthreads();
        if (tid == 0) {
            __threadfence();
            atomicAdd(&g_scanDone, 1);
        }
    }

    if (tid == 0) {
        while (atomicAdd(&g_scanDone, 0) < 2) __nanosleep(100);
    }
    __syncthreads();

    int base = blockIdx.x * blockDim.x * 4 + tid;
    int e[4], r[4], c[4];
    u32 vb[4];
    bool ok[4];
#pragma unroll
    for (int j = 0; j < 4; j++) {
        e[j] = base + j * blockDim.x;
        ok[j] = e[j] < nnz;
        if (ok[j]) {
            r[j] = row[e[j]];
            c[j] = col[e[j]];
            vb[j] = __float_as_uint(fabsf(av[e[j]]));
        }
    }
    int p[4], q[4];
#pragma unroll
    for (int j = 0; j < 4; j++) {
        if (ok[j]) {
            p[j] = atomicAdd(&g_curC[c[j]], 1);
            q[j] = atomicAdd(&g_curV[r[j]], 1);
        }
    }
#pragma unroll
    for (int j = 0; j < 4; j++) {
        if (ok[j]) {
            g_cscE[p[j]] = ((u64)vb[j] << 32) | (u32)(r[j] * FM);
            g_csrE[q[j]] = ((u64)vb[j] << 32) | (u32)(c[j] * FM);
        }
    }
}

// ===================== segment gather-reduce (warp per segment) ============
__global__ void seg_gather_kernel(const int* __restrict__ offs,
                                  const u64* __restrict__ edges,
                                  const float* __restrict__ srcF,
                                  float* __restrict__ dstF, int nseg) {
    int warp = threadIdx.x >> 5;
    int lane = threadIdx.x & 31;
    int seg  = blockIdx.x * (blockDim.x >> 5) + warp;
    if (seg >= nseg) return;

    const float* src2 = srcF + 2 * lane;

    int s = offs[seg], e = offs[seg + 1];
    float ax = 0.f, ay = 0.f;
    int p = s;
    for (; p + 4 <= e; p += 4) {
        u64 e0 = __ldg(&edges[p + 0]);
        u64 e1 = __ldg(&edges[p + 1]);
        u64 e2 = __ldg(&edges[p + 2]);
        u64 e3 = __ldg(&edges[p + 3]);
        float2 f0 = *(const float2*)&src2[(u32)e0];
        float2 f1 = *(const float2*)&src2[(u32)e1];
        float2 f2 = *(const float2*)&src2[(u32)e2];
        float2 f3 = *(const float2*)&src2[(u32)e3];
        float v0 = __uint_as_float((u32)(e0 >> 32));
        float v1 = __uint_as_float((u32)(e1 >> 32));
        float v2 = __uint_as_float((u32)(e2 >> 32));
        float v3 = __uint_as_float((u32)(e3 >> 32));
        ax += v0 * f0.x; ay += v0 * f0.y;
        ax += v1 * f1.x; ay += v1 * f1.y;
        ax += v2 * f2.x; ay += v2 * f2.y;
        ax += v3 * f3.x; ay += v3 * f3.y;
    }
    for (; p < e; p++) {
        u64 e0 = __ldg(&edges[p]);
        float2 f0 = *(const float2*)&src2[(u32)e0];
        float v0 = __uint_as_float((u32)(e0 >> 32));
        ax += v0 * f0.x; ay += v0 * f0.y;
    }
    *(float2*)&dstF[(size_t)seg * FM + 2 * lane] = make_float2(ax, ay);
}

// ===================== MMA MLP: concat(inA,inB)->128(relu)->64 ==============
// Register-lean version: layer-1 computed in two 64-col halves, each half
// immediately consumed by 4 layer-2 k-chunks (d1 live regs 64 -> 32).
// __launch_bounds__(256, 2) forces <=128 regs -> 2 CTAs/SM.
__global__ void __launch_bounds__(256, 2) mlp_mma_kernel(
        const float* __restrict__ inA, const float* __restrict__ inB,
        float* __restrict__ outp,
        const uint4* __restrict__ w1p, const float* __restrict__ b1,
        const uint4* __restrict__ w2p, const float* __restrict__ b2,
        int rows) {
    int tid = threadIdx.x;
    int wid = tid >> 5;
    int lane = tid & 31;
    int m = lane & 3;
    int g = lane >> 2;

    int rbase = blockIdx.x * 128 + wid * 16;
    if (rbase >= rows) return;
    int r0 = rbase + g, r1 = rbase + g + 8;
    int rr0 = min(r0, rows - 1), rr1 = min(r1, rows - 1);

    float d2[8][4];
#pragma unroll
    for (int j = 0; j < 8; j++)
#pragma unroll
        for (int q = 0; q < 4; q++) d2[j][q] = 0.f;

#pragma unroll
    for (int half = 0; half < 2; half++) {
        // ---- layer 1: d1 columns [half*64, half*64+64) over full K ----
        float d1[8][4];
#pragma unroll
        for (int j = 0; j < 8; j++)
#pragma unroll
            for (int q = 0; q < 4; q++) d1[j][q] = 0.f;

#pragma unroll
        for (int t = 0; t < 8; t++) {
            const float* src = (t < 4) ? inA : inB;
            int kc = (t & 3) * 16 + 2 * m;
            float2 x0 = *(const float2*)&src[(size_t)rr0 * 64 + kc];
            float2 x1 = *(const float2*)&src[(size_t)rr1 * 64 + kc];
            float2 x2 = *(const float2*)&src[(size_t)rr0 * 64 + kc + 8];
            float2 x3 = *(const float2*)&src[(size_t)rr1 * 64 + kc + 8];
            u32 ah0, al0, ah1, al1, ah2, al2, ah3, al3;
            bfsplit2(x0.x, x0.y, ah0, al0);
            bfsplit2(x1.x, x1.y, ah1, al1);
            bfsplit2(x2.x, x2.y, ah2, al2);
            bfsplit2(x3.x, x3.y, ah3, al3);

            const uint4* wp = w1p + (size_t)(t * 16 + half * 8) * 32 + lane;
#pragma unroll
            for (int j = 0; j < 8; j++) {
                uint4 w = __ldg(&wp[j * 32]);
                mma_bf16(d1[j], ah0, ah1, ah2, ah3, w.x, w.y);
                mma_bf16(d1[j], ah0, ah1, ah2, ah3, w.z, w.w);
                mma_bf16(d1[j], al0, al1, al2, al3, w.x, w.y);
            }
        }

        // ---- layer 2: chunks t2 = half*4 .. half*4+3 consume d1 pairs ----
#pragma unroll
        for (int u = 0; u < 4; u++) {
            int t2 = half * 4 + u;
            float2 ba = *(const float2*)&b1[16 * t2 + 2 * m];
            float2 bb = *(const float2*)&b1[16 * t2 + 8 + 2 * m];
            float f0 = fmaxf(d1[2 * u][0] + ba.x, 0.f);
            float f1 = fmaxf(d1[2 * u][1] + ba.y, 0.f);
            float f2 = fmaxf(d1[2 * u][2] + ba.x, 0.f);
            float f3 = fmaxf(d1[2 * u][3] + ba.y, 0.f);
            float f4 = fmaxf(d1[2 * u + 1][0] + bb.x, 0.f);
            float f5 = fmaxf(d1[2 * u + 1][1] + bb.y, 0.f);
            float f6 = fmaxf(d1[2 * u + 1][2] + bb.x, 0.f);
            float f7 = fmaxf(d1[2 * u + 1][3] + bb.y, 0.f);
            u32 ah0, al0, ah1, al1, ah2, al2, ah3, al3;
            bfsplit2(f0, f1, ah0, al0);
            bfsplit2(f2, f3, ah1, al1);
            bfsplit2(f4, f5, ah2, al2);
            bfsplit2(f6, f7, ah3, al3);

            const uint4* wp = w2p + (size_t)(t2 * 8) * 32 + lane;
#pragma unroll
            for (int j = 0; j < 8; j++) {
                uint4 w = __ldg(&wp[j * 32]);
                mma_bf16(d2[j], ah0, ah1, ah2, ah3, w.x, w.y);
                mma_bf16(d2[j], ah0, ah1, ah2, ah3, w.z, w.w);
                mma_bf16(d2[j], al0, al1, al2, al3, w.x, w.y);
            }
        }
    }

#pragma unroll
    for (int j = 0; j < 8; j++) {
        float2 b = *(const float2*)&b2[8 * j + 2 * m];
        if (r0 < rows) {
            *(float2*)&outp[(size_t)r0 * 64 + 8 * j + 2 * m] =
                make_float2(d2[j][0] + b.x, d2[j][1] + b.y);
        }
        if (r1 < rows) {
            *(float2*)&outp[(size_t)r1 * 64 + 8 * j + 2 * m] =
                make_float2(d2[j][2] + b.x, d2[j][3] + b.y);
        }
    }
}

// ===================== MMA output MLP: vars[64]->128(relu)->16 + sigmoid ====
__global__ void __launch_bounds__(256, 2) out_mma_kernel(
        const uint4* __restrict__ w1p, const float* __restrict__ b1,
        const uint4* __restrict__ w2p, const float* __restrict__ b2,
        float* __restrict__ outp, int rows) {
    int tid = threadIdx.x;
    int wid = tid >> 5;
    int lane = tid & 31;
    int m = lane & 3;
    int g = lane >> 2;

    int rbase = blockIdx.x * 128 + wid * 16;
    if (rbase >= rows) return;
    int r0 = rbase + g, r1 = rbase + g + 8;
    int rr0 = min(r0, rows - 1), rr1 = min(r1, rows - 1);

    float d2[2][4];
#pragma unroll
    for (int j = 0; j < 2; j++)
#pragma unroll
        for (int q = 0; q < 4; q++) d2[j][q] = 0.f;

#pragma unroll
    for (int half = 0; half < 2; half++) {
        float d1[8][4];
#pragma unroll
        for (int j = 0; j < 8; j++)
#pragma unroll
            for (int q = 0; q < 4; q++) d1[j][q] = 0.f;

#pragma unroll
        for (int t = 0; t < 4; t++) {
            int kc = t * 16 + 2 * m;
            float2 x0 = *(const float2*)&g_vars[(size_t)rr0 * 64 + kc];
            float2 x1 = *(const float2*)&g_vars[(size_t)rr1 * 64 + kc];
            float2 x2 = *(const float2*)&g_vars[(size_t)rr0 * 64 + kc + 8];
            float2 x3 = *(const float2*)&g_vars[(size_t)rr1 * 64 + kc + 8];
            u32 ah0, al0, ah1, al1, ah2, al2, ah3, al3;
            bfsplit2(x0.x, x0.y, ah0, al0);
            bfsplit2(x1.x, x1.y, ah1, al1);
            bfsplit2(x2.x, x2.y, ah2, al2);
            bfsplit2(x3.x, x3.y, ah3, al3);

            const uint4* wp = w1p + (size_t)(t * 16 + half * 8) * 32 + lane;
#pragma unroll
            for (int j = 0; j < 8; j++) {
                uint4 w = __ldg(&wp[j * 32]);
                mma_bf16(d1[j], ah0, ah1, ah2, ah3, w.x, w.y);
                mma_bf16(d1[j], ah0, ah1, ah2, ah3, w.z, w.w);
                mma_bf16(d1[j], al0, al1, al2, al3, w.x, w.y);
            }
        }

#pragma unroll
        for (int u = 0; u < 4; u++) {
            int t2 = half * 4 + u;
            float2 ba = *(const float2*)&b1[16 * t2 + 2 * m];
            float2 bb = *(const float2*)&b1[16 * t2 + 8 + 2 * m];
            float f0 = fmaxf(d1[2 * u][0] + ba.x, 0.f);
            float f1 = fmaxf(d1[2 * u][1] + ba.y, 0.f);
            float f2 = fmaxf(d1[2 * u][2] + ba.x, 0.f);
            float f3 = fmaxf(d1[2 * u][3] + ba.y, 0.f);
            float f4 = fmaxf(d1[2 * u + 1][0] + bb.x, 0.f);
            float f5 = fmaxf(d1[2 * u + 1][1] + bb.y, 0.f);
            float f6 = fmaxf(d1[2 * u + 1][2] + bb.x, 0.f);
            float f7 = fmaxf(d1[2 * u + 1][3] + bb.y, 0.f);
            u32 ah0, al0, ah1, al1, ah2, al2, ah3, al3;
            bfsplit2(f0, f1, ah0, al0);
            bfsplit2(f2, f3, ah1, al1);
            bfsplit2(f4, f5, ah2, al2);
            bfsplit2(f6, f7, ah3, al3);

            const uint4* wp = w2p + (size_t)(t2 * 2) * 32 + lane;
#pragma unroll
            for (int j = 0; j < 2; j++) {
                uint4 w = __ldg(&wp[j * 32]);
                mma_bf16(d2[j], ah0, ah1, ah2, ah3, w.x, w.y);
                mma_bf16(d2[j], ah0, ah1, ah2, ah3, w.z, w.w);
                mma_bf16(d2[j], al0, al1, al2, al3, w.x, w.y);
            }
        }
    }

#pragma unroll
    for (int j = 0; j < 2; j++) {
        float2 b = *(const float2*)&b2[8 * j + 2 * m];
        if (r0 < rows) {
            float z0 = d2[j][0] + b.x;
            float z1 = d2[j][1] + b.y;
            *(float2*)&outp[(size_t)r0 * OUTB + 8 * j + 2 * m] =
                make_float2(1.f / (1.f + __expf(-z0)), 1.f / (1.f + __expf(-z1)));
        }
        if (r1 < rows) {
            float z2 = d2[j][2] + b.x;
            float z3 = d2[j][3] + b.y;
            *(float2*)&outp[(size_t)r1 * OUTB + 8 * j + 2 * m] =
                make_float2(1.f / (1.f + __expf(-z2)), 1.f / (1.f + __expf(-z3)));
        }
    }
}

// ===================== launch ===============================================
extern "C" void kernel_launch(void* const* d_in, const int* in_sizes, int n_in,
                              void* d_out, int out_size) {
    const int*   row  = (const int*)  d_in[0];
    const int*   col  = (const int*)  d_in[1];
    const float* adj  = (const float*)d_in[2];
    const float* cond = (const float*)d_in[3];

    int nnz = in_sizes[0];
    int C   = in_sizes[3];
    int V   = out_size / OUTB;
    if (nnz > MAXNNZ) nnz = MAXNNZ;
    if (C > MAXC) C = MAXC;
    if (V > MAXV) V = MAXV;

    int w = 4;
    if (n_in >= 22 && in_sizes[4] == 1 && in_sizes[5] == 1) w = 6;
    const float* pc_w1 = (const float*)d_in[w + 0];
    const float* pc_b1 = (const float*)d_in[w + 1];
    const float* pc_w2 = (const float*)d_in[w + 2];
    const float* pc_b2 = (const float*)d_in[w + 3];
    const float* cu_w1 = (const float*)d_in[w + 4];
    const float* cu_b1 = (const float*)d_in[w + 5];
    const float* cu_w2 = (const float*)d_in[w + 6];
    const float* cu_b2 = (const float*)d_in[w + 7];
    const float* vu_w1 = (const float*)d_in[w + 8];
    const float* vu_b1 = (const float*)d_in[w + 9];
    const float* vu_w2 = (const float*)d_in[w + 10];
    const float* vu_b2 = (const float*)d_in[w + 11];
    const float* o_w1  = (const float*)d_in[w + 12];
    const float* o_b1  = (const float*)d_in[w + 13];
    const float* o_w2  = (const float*)d_in[w + 14];
    const float* o_b2  = (const float*)d_in[w + 15];

    float *p_vars, *p_cons, *p_v2c, *p_c2v;
    int   *p_offC, *p_offV;
    u64   *p_cscE, *p_csrE;
    u32   *p_w1cu, *p_w2cu, *p_w1vu, *p_w2vu, *p_w1o, *p_w2o;
    cudaGetSymbolAddress((void**)&p_vars,  g_vars);
    cudaGetSymbolAddress((void**)&p_cons,  g_cons);
    cudaGetSymbolAddress((void**)&p_v2c,   g_v2c);
    cudaGetSymbolAddress((void**)&p_c2v,   g_c2v);
    cudaGetSymbolAddress((void**)&p_offC,  g_offC);
    cudaGetSymbolAddress((void**)&p_offV,  g_offV);
    cudaGetSymbolAddress((void**)&p_cscE,  g_cscE);
    cudaGetSymbolAddress((void**)&p_csrE,  g_csrE);
    cudaGetSymbolAddress((void**)&p_w1cu,  g_w1p_cu);
    cudaGetSymbolAddress((void**)&p_w2cu,  g_w2p_cu);
    cudaGetSymbolAddress((void**)&p_w1vu,  g_w1p_vu);
    cudaGetSymbolAddress((void**)&p_w2vu,  g_w2p_vu);
    cudaGetSymbolAddress((void**)&p_w1o,   g_w1p_out);
    cudaGetSymbolAddress((void**)&p_w2o,   g_w2p_out);

    int maxCV = (C > V) ? C : V;
    int gZ = (maxCV + 255) / 256;
    int gI = (V * FM + 255) / 256;
    int gP = (C + 31) / 32;
    int gridSetup = gZ + gI + 128 + 32 + gP;

    setup_kernel<<<gridSetup, 256>>>(gZ, gI, gP, C, V, cond,
                                     pc_w1, pc_b1, pc_w2, pc_b2,
                                     cu_w1, cu_w2, vu_w1, vu_w2, o_w1, o_w2);
    hist_kernel<<<(nnz + 2047) / 2048, 256>>>(row, col, nnz);
    fill_kernel<<<(nnz + 1023) / 1024, 256>>>(row, col, adj, nnz, C, V);

    int gC = (C + 127) / 128;
    int gV = (V + 127) / 128;
    for (int it = 0; it < 3; it++) {
        seg_gather_kernel<<<(C + 7) / 8, 256>>>(p_offC, p_cscE, p_vars, p_v2c, C);
        mlp_mma_kernel<<<gC, 256>>>(p_cons, p_v2c, p_cons,
                                    (const uint4*)p_w1cu, cu_b1, (const uint4*)p_w2cu, cu_b2, C);
        seg_gather_kernel<<<(V + 7) / 8, 256>>>(p_offV, p_csrE, p_cons, p_c2v, V);
        mlp_mma_kernel<<<gV, 256>>>(p_vars, p_c2v, p_vars,
                                    (const uint4*)p_w1vu, vu_b1, (const uint4*)p_w2vu, vu_b2, V);
    }

    out_mma_kernel<<<(V + 127) / 128, 256>>>((const uint4*)p_w1o, o_b1,
                                             (const uint4*)p_w2o, o_b2,
                                             (float*)d_out, V);
}

// round 17
// speedup vs baseline: 1.0622x; 1.0033x over previous
#include <cuda_runtime.h>
#include <cuda_bf16.h>
#include <cstdint>

#define FM        64
#define MAXV      100000
#define MAXC      50000
#define MAXNNZ    2000000
#define OUTB      16

typedef unsigned long long u64;
typedef unsigned int u32;

// ===================== scratch globals ======================================
__device__ float g_vars[MAXV * FM];
__device__ float g_cons[MAXC * FM];
__device__ float g_v2c [MAXC * FM];
__device__ float g_c2v [MAXV * FM];

__device__ int   g_cntC[MAXC];
__device__ int   g_cntV[MAXV];
__device__ int   g_offC[MAXC + 1];
__device__ int   g_offV[MAXV + 1];
__device__ int   g_curC[MAXC];
__device__ int   g_curV[MAXV];

__device__ int   g_scanDone;

// packed edge entries: low 32 = feature-row offset (index*FM), high 32 = |val| bits
__device__ __align__(16) u64 g_cscE[MAXNNZ];
__device__ __align__(16) u64 g_csrE[MAXNNZ];

// packed per-lane weight fragments (uint4 = {b0_hi, b1_hi, b0_lo, b1_lo})
__device__ u32 g_w1p_cu[16384];
__device__ u32 g_w2p_cu[8192];
__device__ u32 g_w1p_vu[16384];
__device__ u32 g_w2p_vu[8192];
__device__ u32 g_w1p_out[8192];
__device__ u32 g_w2p_out[2048];

// ===================== helpers ==============================================
__device__ __forceinline__ void bfsplit2(float f0, float f1, u32& hi, u32& lo) {
    __nv_bfloat162 h, l;
    h.x = __float2bfloat16(f0);
    h.y = __float2bfloat16(f1);
    l.x = __float2bfloat16(f0 - __bfloat162float(h.x));
    l.y = __float2bfloat16(f1 - __bfloat162float(h.y));
    hi = *(u32*)&h;
    lo = *(u32*)&l;
}

__device__ __forceinline__ void mma_bf16(float* d, u32 a0, u32 a1, u32 a2, u32 a3,
                                         u32 b0, u32 b1) {
    asm volatile(
        "mma.sync.aligned.m16n8k16.row.col.f32.bf16.bf16.f32 "
        "{%0,%1,%2,%3}, {%4,%5,%6,%7}, {%8,%9}, {%0,%1,%2,%3};"
        : "+f"(d[0]), "+f"(d[1]), "+f"(d[2]), "+f"(d[3])
        : "r"(a0), "r"(a1), "r"(a2), "r"(a3), "r"(b0), "r"(b1));
}

// scalar layer-2 helper for the prep branch of the setup kernel
__device__ __forceinline__ void mlp_layer2_64(const float* sbuf,
                                              const float* __restrict__ W2,
                                              const float* __restrict__ b2,
                                              float* __restrict__ outp,
                                              int row0, int rows, int lane) {
    float2 acc[4];
#pragma unroll
    for (int r = 0; r < 4; r++) acc[r] = make_float2(0.f, 0.f);

    for (int k = 0; k < 128; k += 4) {
        float4 hv[4];
#pragma unroll
        for (int r = 0; r < 4; r++) hv[r] = *(const float4*)&sbuf[r * 128 + k];
#pragma unroll
        for (int kk = 0; kk < 4; kk++) {
            float2 w = *(const float2*)&W2[(k + kk) * 64 + 2 * lane];
#pragma unroll
            for (int r = 0; r < 4; r++) {
                float hk = ((const float*)&hv[r])[kk];
                acc[r].x += hk * w.x;
                acc[r].y += hk * w.y;
            }
        }
    }
    float2 bb = *(const float2*)&b2[2 * lane];
#pragma unroll
    for (int r = 0; r < 4; r++) {
        if (row0 + r < rows) {
            *(float2*)&outp[(size_t)(row0 + r) * 64 + 2 * lane] =
                make_float2(acc[r].x + bb.x, acc[r].y + bb.y);
        }
    }
}

// ===================== fused setup kernel ====================================
__global__ void __launch_bounds__(256) setup_kernel(
        int gZ, int gI, int gP, int C, int V,
        const float* __restrict__ cond,
        const float* __restrict__ pc_w1, const float* __restrict__ pc_b1,
        const float* __restrict__ pc_w2, const float* __restrict__ pc_b2,
        const float* __restrict__ cu_w1, const float* __restrict__ cu_w2,
        const float* __restrict__ vu_w1, const float* __restrict__ vu_w2,
        const float* __restrict__ o_w1,  const float* __restrict__ o_w2) {
    __shared__ float sbuf[8][512];
    int b   = blockIdx.x;
    int tid = threadIdx.x;

    if (b == 0 && tid == 0) g_scanDone = 0;

    if (b < gZ) {
        int i = b * 256 + tid;
        if (i < C) g_cntC[i] = 0;
        if (i < V) g_cntV[i] = 0;
        return;
    }
    b -= gZ;

    if (b < gI) {
        int i = b * 256 + tid;
        if (i < V * FM) g_vars[i] = 1.0f;
        return;
    }
    b -= gI;

    if (b < 128) {   // conv_w for cu (first 64 blocks) and vu (next 64)
        const float* W1 = (b < 64) ? cu_w1 : vu_w1;
        const float* W2 = (b < 64) ? cu_w2 : vu_w2;
        u32* w1p = (b < 64) ? g_w1p_cu : g_w1p_vu;
        u32* w2p = (b < 64) ? g_w2p_cu : g_w2p_vu;
        int idx = (b & 63) * 256 + tid;     // 0..16383
        {
            int pos  = idx & 3;
            int lane = (idx >> 2) & 31;
            int j    = (idx >> 7) & 15;
            int t    = idx >> 11;
            int k = t * 16 + 2 * (lane & 3) + ((pos & 1) ? 8 : 0);
            int n = j * 8 + (lane >> 2);
            float f0 = W1[k * 128 + n];
            float f1 = W1[(k + 1) * 128 + n];
            u32 hi, lo;
            bfsplit2(f0, f1, hi, lo);
            w1p[idx] = (pos >= 2) ? lo : hi;
        }
        if (idx < 8192) {
            int pos  = idx & 3;
            int lane = (idx >> 2) & 31;
            int j    = (idx >> 7) & 7;
            int t    = idx >> 10;
            int k = t * 16 + 2 * (lane & 3) + ((pos & 1) ? 8 : 0);
            int n = j * 8 + (lane >> 2);
            float f0 = W2[k * 64 + n];
            float f1 = W2[(k + 1) * 64 + n];
            u32 hi, lo;
            bfsplit2(f0, f1, hi, lo);
            w2p[idx] = (pos >= 2) ? lo : hi;
        }
        return;
    }
    b -= 128;

    if (b < 32) {    // conv_w_out
        int idx = b * 256 + tid;            // 0..8191
        {
            int pos  = idx & 3;
            int lane = (idx >> 2) & 31;
            int j    = (idx >> 7) & 15;
            int t    = idx >> 11;           // 0..3
            int k = t * 16 + 2 * (lane & 3) + ((pos & 1) ? 8 : 0);
            int n = j * 8 + (lane >> 2);
            float f0 = o_w1[k * 128 + n];
            float f1 = o_w1[(k + 1) * 128 + n];
            u32 hi, lo;
            bfsplit2(f0, f1, hi, lo);
            g_w1p_out[idx] = (pos >= 2) ? lo : hi;
        }
        if (idx < 2048) {
            int pos  = idx & 3;
            int lane = (idx >> 2) & 31;
            int j    = (idx >> 7) & 1;
            int t    = idx >> 8;            // 0..7
            int k = t * 16 + 2 * (lane & 3) + ((pos & 1) ? 8 : 0);
            int n = j * 8 + (lane >> 2);
            float f0 = o_w2[k * 16 + n];
            float f1 = o_w2[(k + 1) * 16 + n];
            u32 hi, lo;
            bfsplit2(f0, f1, hi, lo);
            g_w2p_out[idx] = (pos >= 2) ? lo : hi;
        }
        return;
    }
    b -= 32;

    if (b < gP) {    // prepare_cond: scalar -> 128(relu) -> 64 into g_cons
        int warp = tid >> 5;
        int lane = tid & 31;
        int row0 = (b * 8 + warp) * 4;
        if (row0 >= C) return;
        float* sbf = sbuf[warp];

        float4 w = *(const float4*)&pc_w1[4 * lane];
        float4 bb = *(const float4*)&pc_b1[4 * lane];
#pragma unroll
        for (int r = 0; r < 4; r++) {
            int row = min(row0 + r, C - 1);
            float c = cond[row];
            float4 h;
            h.x = fmaxf(c * w.x + bb.x, 0.f);
            h.y = fmaxf(c * w.y + bb.y, 0.f);
            h.z = fmaxf(c * w.z + bb.z, 0.f);
            h.w = fmaxf(c * w.w + bb.w, 0.f);
            *(float4*)&sbf[r * 128 + 4 * lane] = h;
        }
        __syncwarp();
        mlp_layer2_64(sbf, pc_w2, pc_b2, g_cons, row0, C, lane);
    }
}

// ===================== CSR/CSC build ========================================
__global__ void hist_kernel(const int* __restrict__ row, const int* __restrict__ col, int nnz) {
    int base = blockIdx.x * blockDim.x * 8 + threadIdx.x;
#pragma unroll
    for (int j = 0; j < 8; j++) {
        int e = base + j * blockDim.x;
        if (e < nnz) {
            atomicAdd(&g_cntC[col[e]], 1);
            atomicAdd(&g_cntV[row[e]], 1);
        }
    }
}

// fill with inlined scan: blocks 0/1 scan C/V sides, publish via flag; all
// blocks then place edges (indices stored PRE-SCALED by FM).
__global__ void __launch_bounds__(256) fill_kernel(
        const int* __restrict__ row, const int* __restrict__ col,
        const float* __restrict__ av, int nnz, int nC, int nV) {
    __shared__ int part[256];
    int tid = threadIdx.x;

    if (blockIdx.x < 2) {
        const int* cnt; int* off; int* cur; int n;
        if (blockIdx.x == 0) { cnt = g_cntC; off = g_offC; cur = g_curC; n = nC; }
        else                 { cnt = g_cntV; off = g_offV; cur = g_curV; n = nV; }

        int chunk = (n + 255) / 256;
        int beg = tid * chunk;
        int end = min(n, beg + chunk);

        int s = 0;
        for (int i = beg; i < end; i++) s += cnt[i];
        part[tid] = s;
        __syncthreads();
        for (int d = 1; d < 256; d <<= 1) {
            int v = (tid >= d) ? part[tid - d] : 0;
            __syncthreads();
            part[tid] += v;
            __syncthreads();
        }
        int run = (tid == 0) ? 0 : part[tid - 1];
        for (int i = beg; i < end; i++) {
            off[i] = run; cur[i] = run;
            run += cnt[i];
        }
        if (tid == 255) off[n] = part[255];
        __syncthreads();
        if (tid == 0) {
            __threadfence();
            atomicAdd(&g_scanDone, 1);
        }
    }

    if (tid == 0) {
        while (atomicAdd(&g_scanDone, 0) < 2) __nanosleep(100);
    }
    __syncthreads();

    int base = blockIdx.x * blockDim.x * 4 + tid;
    int e[4], r[4], c[4];
    u32 vb[4];
    bool ok[4];
#pragma unroll
    for (int j = 0; j < 4; j++) {
        e[j] = base + j * blockDim.x;
        ok[j] = e[j] < nnz;
        if (ok[j]) {
            r[j] = row[e[j]];
            c[j] = col[e[j]];
            vb[j] = __float_as_uint(fabsf(av[e[j]]));
        }
    }
    int p[4], q[4];
#pragma unroll
    for (int j = 0; j < 4; j++) {
        if (ok[j]) {
            p[j] = atomicAdd(&g_curC[c[j]], 1);
            q[j] = atomicAdd(&g_curV[r[j]], 1);
        }
    }
#pragma unroll
    for (int j = 0; j < 4; j++) {
        if (ok[j]) {
            g_cscE[p[j]] = ((u64)vb[j] << 32) | (u32)(r[j] * FM);
            g_csrE[q[j]] = ((u64)vb[j] << 32) | (u32)(c[j] * FM);
        }
    }
}

// ===================== segment gather-reduce (warp per segment) ============
// Edge low-32 is pre-scaled (index*FM). Edges loaded 2-at-a-time via LDG.128
// (arrays 16B-aligned; odd segment starts peeled).
__global__ void seg_gather_kernel(const int* __restrict__ offs,
                                  const u64* __restrict__ edges,
                                  const float* __restrict__ srcF,
                                  float* __restrict__ dstF, int nseg) {
    int warp = threadIdx.x >> 5;
    int lane = threadIdx.x & 31;
    int seg  = blockIdx.x * (blockDim.x >> 5) + warp;
    if (seg >= nseg) return;

    const float* src2 = srcF + 2 * lane;

    int s = offs[seg], e = offs[seg + 1];
    float ax = 0.f, ay = 0.f;
    int p = s;

    if (p < e && (p & 1)) {
        u64 e0 = __ldg(&edges[p]);
        float2 f0 = *(const float2*)&src2[(u32)e0];
        float v0 = __uint_as_float((u32)(e0 >> 32));
        ax += v0 * f0.x; ay += v0 * f0.y;
        p++;
    }
    for (; p + 4 <= e; p += 4) {
        uint4 a = __ldg((const uint4*)&edges[p]);
        uint4 b = __ldg((const uint4*)&edges[p + 2]);
        float2 f0 = *(const float2*)&src2[a.x];
        float2 f1 = *(const float2*)&src2[a.z];
        float2 f2 = *(const float2*)&src2[b.x];
        float2 f3 = *(const float2*)&src2[b.z];
        float v0 = __uint_as_float(a.y);
        float v1 = __uint_as_float(a.w);
        float v2 = __uint_as_float(b.y);
        float v3 = __uint_as_float(b.w);
        ax += v0 * f0.x; ay += v0 * f0.y;
        ax += v1 * f1.x; ay += v1 * f1.y;
        ax += v2 * f2.x; ay += v2 * f2.y;
        ax += v3 * f3.x; ay += v3 * f3.y;
    }
    if (p + 2 <= e) {
        uint4 a = __ldg((const uint4*)&edges[p]);
        float2 f0 = *(const float2*)&src2[a.x];
        float2 f1 = *(const float2*)&src2[a.z];
        float v0 = __uint_as_float(a.y);
        float v1 = __uint_as_float(a.w);
        ax += v0 * f0.x; ay += v0 * f0.y;
        ax += v1 * f1.x; ay += v1 * f1.y;
        p += 2;
    }
    if (p < e) {
        u64 e0 = __ldg(&edges[p]);
        float2 f0 = *(const float2*)&src2[(u32)e0];
        float v0 = __uint_as_float((u32)(e0 >> 32));
        ax += v0 * f0.x; ay += v0 * f0.y;
    }
    *(float2*)&dstF[(size_t)seg * FM + 2 * lane] = make_float2(ax, ay);
}

// ===================== MMA MLP: concat(inA,inB)->128(relu)->64 ==============
// Register-lean: layer-1 in two 64-col halves; __launch_bounds__(256,2).
__global__ void __launch_bounds__(256, 2) mlp_mma_kernel(
        const float* __restrict__ inA, const float* __restrict__ inB,
        float* __restrict__ outp,
        const uint4* __restrict__ w1p, const float* __restrict__ b1,
        const uint4* __restrict__ w2p, const float* __restrict__ b2,
        int rows) {
    int tid = threadIdx.x;
    int wid = tid >> 5;
    int lane = tid & 31;
    int m = lane & 3;
    int g = lane >> 2;

    int rbase = blockIdx.x * 128 + wid * 16;
    if (rbase >= rows) return;
    int r0 = rbase + g, r1 = rbase + g + 8;
    int rr0 = min(r0, rows - 1), rr1 = min(r1, rows - 1);

    float d2[8][4];
#pragma unroll
    for (int j = 0; j < 8; j++)
#pragma unroll
        for (int q = 0; q < 4; q++) d2[j][q] = 0.f;

#pragma unroll
    for (int half = 0; half < 2; half++) {
        float d1[8][4];
#pragma unroll
        for (int j = 0; j < 8; j++)
#pragma unroll
            for (int q = 0; q < 4; q++) d1[j][q] = 0.f;

#pragma unroll
        for (int t = 0; t < 8; t++) {
            const float* src = (t < 4) ? inA : inB;
            int kc = (t & 3) * 16 + 2 * m;
            float2 x0 = *(const float2*)&src[(size_t)rr0 * 64 + kc];
            float2 x1 = *(const float2*)&src[(size_t)rr1 * 64 + kc];
            float2 x2 = *(const float2*)&src[(size_t)rr0 * 64 + kc + 8];
            float2 x3 = *(const float2*)&src[(size_t)rr1 * 64 + kc + 8];
            u32 ah0, al0, ah1, al1, ah2, al2, ah3, al3;
            bfsplit2(x0.x, x0.y, ah0, al0);
            bfsplit2(x1.x, x1.y, ah1, al1);
            bfsplit2(x2.x, x2.y, ah2, al2);
            bfsplit2(x3.x, x3.y, ah3, al3);

            const uint4* wp = w1p + (size_t)(t * 16 + half * 8) * 32 + lane;
#pragma unroll
            for (int j = 0; j < 8; j++) {
                uint4 w = __ldg(&wp[j * 32]);
                mma_bf16(d1[j], ah0, ah1, ah2, ah3, w.x, w.y);
                mma_bf16(d1[j], ah0, ah1, ah2, ah3, w.z, w.w);
                mma_bf16(d1[j], al0, al1, al2, al3, w.x, w.y);
            }
        }

#pragma unroll
        for (int u = 0; u < 4; u++) {
            int t2 = half * 4 + u;
            float2 ba = *(const float2*)&b1[16 * t2 + 2 * m];
            float2 bb = *(const float2*)&b1[16 * t2 + 8 + 2 * m];
            float f0 = fmaxf(d1[2 * u][0] + ba.x, 0.f);
            float f1 = fmaxf(d1[2 * u][1] + ba.y, 0.f);
            float f2 = fmaxf(d1[2 * u][2] + ba.x, 0.f);
            float f3 = fmaxf(d1[2 * u][3] + ba.y, 0.f);
            float f4 = fmaxf(d1[2 * u + 1][0] + bb.x, 0.f);
            float f5 = fmaxf(d1[2 * u + 1][1] + bb.y, 0.f);
            float f6 = fmaxf(d1[2 * u + 1][2] + bb.x, 0.f);
            float f7 = fmaxf(d1[2 * u + 1][3] + bb.y, 0.f);
            u32 ah0, al0, ah1, al1, ah2, al2, ah3, al3;
            bfsplit2(f0, f1, ah0, al0);
            bfsplit2(f2, f3, ah1, al1);
            bfsplit2(f4, f5, ah2, al2);
            bfsplit2(f6, f7, ah3, al3);

            const uint4* wp = w2p + (size_t)(t2 * 8) * 32 + lane;
#pragma unroll
            for (int j = 0; j < 8; j++) {
                uint4 w = __ldg(&wp[j * 32]);
                mma_bf16(d2[j], ah0, ah1, ah2, ah3, w.x, w.y);
                mma_bf16(d2[j], ah0, ah1, ah2, ah3, w.z, w.w);
                mma_bf16(d2[j], al0, al1, al2, al3, w.x, w.y);
            }
        }
    }

#pragma unroll
    for (int j = 0; j < 8; j++) {
        float2 b = *(const float2*)&b2[8 * j + 2 * m];
        if (r0 < rows) {
            *(float2*)&outp[(size_t)r0 * 64 + 8 * j + 2 * m] =
                make_float2(d2[j][0] + b.x, d2[j][1] + b.y);
        }
        if (r1 < rows) {
            *(float2*)&outp[(size_t)r1 * 64 + 8 * j + 2 * m] =
                make_float2(d2[j][2] + b.x, d2[j][3] + b.y);
        }
    }
}

// ===================== MMA output MLP: vars[64]->128(relu)->16 + sigmoid ====
__global__ void __launch_bounds__(256, 2) out_mma_kernel(
        const uint4* __restrict__ w1p, const float* __restrict__ b1,
        const uint4* __restrict__ w2p, const float* __restrict__ b2,
        float* __restrict__ outp, int rows) {
    int tid = threadIdx.x;
    int wid = tid >> 5;
    int lane = tid & 31;
    int m = lane & 3;
    int g = lane >> 2;

    int rbase = blockIdx.x * 128 + wid * 16;
    if (rbase >= rows) return;
    int r0 = rbase + g, r1 = rbase + g + 8;
    int rr0 = min(r0, rows - 1), rr1 = min(r1, rows - 1);

    float d2[2][4];
#pragma unroll
    for (int j = 0; j < 2; j++)
#pragma unroll
        for (int q = 0; q < 4; q++) d2[j][q] = 0.f;

#pragma unroll
    for (int half = 0; half < 2; half++) {
        float d1[8][4];
#pragma unroll
        for (int j = 0; j < 8; j++)
#pragma unroll
            for (int q = 0; q < 4; q++) d1[j][q] = 0.f;

#pragma unroll
        for (int t = 0; t < 4; t++) {
            int kc = t * 16 + 2 * m;
            float2 x0 = *(const float2*)&g_vars[(size_t)rr0 * 64 + kc];
            float2 x1 = *(const float2*)&g_vars[(size_t)rr1 * 64 + kc];
            float2 x2 = *(const float2*)&g_vars[(size_t)rr0 * 64 + kc + 8];
            float2 x3 = *(const float2*)&g_vars[(size_t)rr1 * 64 + kc + 8];
            u32 ah0, al0, ah1, al1, ah2, al2, ah3, al3;
            bfsplit2(x0.x, x0.y, ah0, al0);
            bfsplit2(x1.x, x1.y, ah1, al1);
            bfsplit2(x2.x, x2.y, ah2, al2);
            bfsplit2(x3.x, x3.y, ah3, al3);

            const uint4* wp = w1p + (size_t)(t * 16 + half * 8) * 32 + lane;
#pragma unroll
            for (int j = 0; j < 8; j++) {
                uint4 w = __ldg(&wp[j * 32]);
                mma_bf16(d1[j], ah0, ah1, ah2, ah3, w.x, w.y);
                mma_bf16(d1[j], ah0, ah1, ah2, ah3, w.z, w.w);
                mma_bf16(d1[j], al0, al1, al2, al3, w.x, w.y);
            }
        }

#pragma unroll
        for (int u = 0; u < 4; u++) {
            int t2 = half * 4 + u;
            float2 ba = *(const float2*)&b1[16 * t2 + 2 * m];
            float2 bb = *(const float2*)&b1[16 * t2 + 8 + 2 * m];
            float f0 = fmaxf(d1[2 * u][0] + ba.x, 0.f);
            float f1 = fmaxf(d1[2 * u][1] + ba.y, 0.f);
            float f2 = fmaxf(d1[2 * u][2] + ba.x, 0.f);
            float f3 = fmaxf(d1[2 * u][3] + ba.y, 0.f);
            float f4 = fmaxf(d1[2 * u + 1][0] + bb.x, 0.f);
            float f5 = fmaxf(d1[2 * u + 1][1] + bb.y, 0.f);
            float f6 = fmaxf(d1[2 * u + 1][2] + bb.x, 0.f);
            float f7 = fmaxf(d1[2 * u + 1][3] + bb.y, 0.f);
            u32 ah0, al0, ah1, al1, ah2, al2, ah3, al3;
            bfsplit2(f0, f1, ah0, al0);
            bfsplit2(f2, f3, ah1, al1);
            bfsplit2(f4, f5, ah2, al2);
            bfsplit2(f6, f7, ah3, al3);

            const uint4* wp = w2p + (size_t)(t2 * 2) * 32 + lane;
#pragma unroll
            for (int j = 0; j < 2; j++) {
                uint4 w = __ldg(&wp[j * 32]);
                mma_bf16(d2[j], ah0, ah1, ah2, ah3, w.x, w.y);
                mma_bf16(d2[j], ah0, ah1, ah2, ah3, w.z, w.w);
                mma_bf16(d2[j], al0, al1, al2, al3, w.x, w.y);
            }
        }
    }

#pragma unroll
    for (int j = 0; j < 2; j++) {
        float2 b = *(const float2*)&b2[8 * j + 2 * m];
        if (r0 < rows) {
            float z0 = d2[j][0] + b.x;
            float z1 = d2[j][1] + b.y;
            *(float2*)&outp[(size_t)r0 * OUTB + 8 * j + 2 * m] =
                make_float2(1.f / (1.f + __expf(-z0)), 1.f / (1.f + __expf(-z1)));
        }
        if (r1 < rows) {
            float z2 = d2[j][2] + b.x;
            float z3 = d2[j][3] + b.y;
            *(float2*)&outp[(size_t)r1 * OUTB + 8 * j + 2 * m] =
                make_float2(1.f / (1.f + __expf(-z2)), 1.f / (1.f + __expf(-z3)));
        }
    }
}

// ===================== launch ===============================================
extern "C" void kernel_launch(void* const* d_in, const int* in_sizes, int n_in,
                              void* d_out, int out_size) {
    const int*   row  = (const int*)  d_in[0];
    const int*   col  = (const int*)  d_in[1];
    const float* adj  = (const float*)d_in[2];
    const float* cond = (const float*)d_in[3];

    int nnz = in_sizes[0];
    int C   = in_sizes[3];
    int V   = out_size / OUTB;
    if (nnz > MAXNNZ) nnz = MAXNNZ;
    if (C > MAXC) C = MAXC;
    if (V > MAXV) V = MAXV;

    int w = 4;
    if (n_in >= 22 && in_sizes[4] == 1 && in_sizes[5] == 1) w = 6;
    const float* pc_w1 = (const float*)d_in[w + 0];
    const float* pc_b1 = (const float*)d_in[w + 1];
    const float* pc_w2 = (const float*)d_in[w + 2];
    const float* pc_b2 = (const float*)d_in[w + 3];
    const float* cu_w1 = (const float*)d_in[w + 4];
    const float* cu_b1 = (const float*)d_in[w + 5];
    const float* cu_w2 = (const float*)d_in[w + 6];
    const float* cu_b2 = (const float*)d_in[w + 7];
    const float* vu_w1 = (const float*)d_in[w + 8];
    const float* vu_b1 = (const float*)d_in[w + 9];
    const float* vu_w2 = (const float*)d_in[w + 10];
    const float* vu_b2 = (const float*)d_in[w + 11];
    const float* o_w1  = (const float*)d_in[w + 12];
    const float* o_b1  = (const float*)d_in[w + 13];
    const float* o_w2  = (const float*)d_in[w + 14];
    const float* o_b2  = (const float*)d_in[w + 15];

    float *p_vars, *p_cons, *p_v2c, *p_c2v;
    int   *p_offC, *p_offV;
    u64   *p_cscE, *p_csrE;
    u32   *p_w1cu, *p_w2cu, *p_w1vu, *p_w2vu, *p_w1o, *p_w2o;
    cudaGetSymbolAddress((void**)&p_vars,  g_vars);
    cudaGetSymbolAddress((void**)&p_cons,  g_cons);
    cudaGetSymbolAddress((void**)&p_v2c,   g_v2c);
    cudaGetSymbolAddress((void**)&p_c2v,   g_c2v);
    cudaGetSymbolAddress((void**)&p_offC,  g_offC);
    cudaGetSymbolAddress((void**)&p_offV,  g_offV);
    cudaGetSymbolAddress((void**)&p_cscE,  g_cscE);
    cudaGetSymbolAddress((void**)&p_csrE,  g_csrE);
    cudaGetSymbolAddress((void**)&p_w1cu,  g_w1p_cu);
    cudaGetSymbolAddress((void**)&p_w2cu,  g_w2p_cu);
    cudaGetSymbolAddress((void**)&p_w1vu,  g_w1p_vu);
    cudaGetSymbolAddress((void**)&p_w2vu,  g_w2p_vu);
    cudaGetSymbolAddress((void**)&p_w1o,   g_w1p_out);
    cudaGetSymbolAddress((void**)&p_w2o,   g_w2p_out);

    int maxCV = (C > V) ? C : V;
    int gZ = (maxCV + 255) / 256;
    int gI = (V * FM + 255) / 256;
    int gP = (C + 31) / 32;
    int gridSetup = gZ + gI + 128 + 32 + gP;

    setup_kernel<<<gridSetup, 256>>>(gZ, gI, gP, C, V, cond,
                                     pc_w1, pc_b1, pc_w2, pc_b2,
                                     cu_w1, cu_w2, vu_w1, vu_w2, o_w1, o_w2);
    hist_kernel<<<(nnz + 2047) / 2048, 256>>>(row, col, nnz);
    fill_kernel<<<(nnz + 1023) / 1024, 256>>>(row, col, adj, nnz, C, V);

    int gC = (C + 127) / 128;
    int gV = (V + 127) / 128;
    for (int it = 0; it < 3; it++) {
        seg_gather_kernel<<<(C + 7) / 8, 256>>>(p_offC, p_cscE, p_vars, p_v2c, C);
        mlp_mma_kernel<<<gC, 256>>>(p_cons, p_v2c, p_cons,
                                    (const uint4*)p_w1cu, cu_b1, (const uint4*)p_w2cu, cu_b2, C);
        seg_gather_kernel<<<(V + 7) / 8, 256>>>(p_offV, p_csrE, p_cons, p_c2v, V);
        mlp_mma_kernel<<<gV, 256>>>(p_vars, p_c2v, p_vars,
                                    (const uint4*)p_w1vu, vu_b1, (const uint4*)p_w2vu, vu_b2, V);
    }

    out_mma_kernel<<<(V + 127) / 128, 256>>>((const uint4*)p_w1o, o_b1,
                                             (const uint4*)p_w2o, o_b2,
                                             (float*)d_out, V);
}